// round 2
// baseline (speedup 1.0000x reference)
#include <cuda_runtime.h>
#include <cuda_bf16.h>
#include <math.h>

#define BB 4096
#define SS 512
#define EE 64
#define MM 16
#define HH 32
#define OUTD 64
#define NSTEPS 5

// Scratch: memories transposed per batch: g_memT[b*MM*SS + m*SS + s]
__device__ float g_memT[(size_t)BB * MM * SS];

// ---------------------------------------------------------------------------
// Kernel 1: memories = MLP(input_set)   E=64 -> 32 -> 32 -> M=16, relu,relu,lin
// One thread per (b,s) row; k-outer accumulation; transposed weights in smem
// (broadcast LDS.128 across the warp -> conflict-free).
// ---------------------------------------------------------------------------
__global__ void __launch_bounds__(256) mem_mlp_kernel(
    const float* __restrict__ x,
    const float* __restrict__ w1, const float* __restrict__ b1,
    const float* __restrict__ w2, const float* __restrict__ b2,
    const float* __restrict__ w3, const float* __restrict__ b3)
{
    __shared__ float sw1T[64 * 32];   // [k][j]
    __shared__ float sw2T[32 * 32];   // [k][j]
    __shared__ float sw3T[32 * 16];   // [k][m]
    __shared__ float sb1[32], sb2[32], sb3[16];

    int tid = threadIdx.x;
    for (int i = tid; i < 2048; i += 256) { int j = i >> 6, k = i & 63; sw1T[k*32 + j] = w1[i]; }
    for (int i = tid; i < 1024; i += 256) { int j = i >> 5, k = i & 31; sw2T[k*32 + j] = w2[i]; }
    for (int i = tid; i < 512;  i += 256) { int m = i >> 5, k = i & 31; sw3T[k*16 + m] = w3[i]; }
    if (tid < 32) { sb1[tid] = b1[tid]; sb2[tid] = b2[tid]; }
    if (tid < 16) sb3[tid] = b3[tid];
    __syncthreads();

    int row = blockIdx.x * 256 + tid;          // exact grid, no bounds check
    const float4* xv = (const float4*)(x + (size_t)row * EE);

    // ---- layer 1: 64 -> 32, relu ----
    float acc[32];
    #pragma unroll
    for (int j = 0; j < 32; j++) acc[j] = sb1[j];

    #pragma unroll
    for (int k4 = 0; k4 < 16; k4++) {
        float4 xc = xv[k4];
        float xs0 = xc.x, xs1 = xc.y, xs2 = xc.z, xs3 = xc.w;
        #pragma unroll
        for (int kk = 0; kk < 4; kk++) {
            float xk = (kk == 0) ? xs0 : (kk == 1) ? xs1 : (kk == 2) ? xs2 : xs3;
            const float4* wv = (const float4*)(sw1T + (k4 * 4 + kk) * 32);
            #pragma unroll
            for (int j4 = 0; j4 < 8; j4++) {
                float4 w = wv[j4];
                acc[4*j4+0] = fmaf(xk, w.x, acc[4*j4+0]);
                acc[4*j4+1] = fmaf(xk, w.y, acc[4*j4+1]);
                acc[4*j4+2] = fmaf(xk, w.z, acc[4*j4+2]);
                acc[4*j4+3] = fmaf(xk, w.w, acc[4*j4+3]);
            }
        }
    }
    float h1[32];
    #pragma unroll
    for (int j = 0; j < 32; j++) h1[j] = fmaxf(acc[j], 0.f);

    // ---- layer 2: 32 -> 32, relu ----
    #pragma unroll
    for (int j = 0; j < 32; j++) acc[j] = sb2[j];
    #pragma unroll
    for (int k = 0; k < 32; k++) {
        float xk = h1[k];
        const float4* wv = (const float4*)(sw2T + k * 32);
        #pragma unroll
        for (int j4 = 0; j4 < 8; j4++) {
            float4 w = wv[j4];
            acc[4*j4+0] = fmaf(xk, w.x, acc[4*j4+0]);
            acc[4*j4+1] = fmaf(xk, w.y, acc[4*j4+1]);
            acc[4*j4+2] = fmaf(xk, w.z, acc[4*j4+2]);
            acc[4*j4+3] = fmaf(xk, w.w, acc[4*j4+3]);
        }
    }
    #pragma unroll
    for (int j = 0; j < 32; j++) h1[j] = fmaxf(acc[j], 0.f);

    // ---- layer 3: 32 -> 16, linear ----
    float o[16];
    #pragma unroll
    for (int m = 0; m < 16; m++) o[m] = sb3[m];
    #pragma unroll
    for (int k = 0; k < 32; k++) {
        float xk = h1[k];
        const float4* wv = (const float4*)(sw3T + k * 16);
        #pragma unroll
        for (int m4 = 0; m4 < 4; m4++) {
            float4 w = wv[m4];
            o[4*m4+0] = fmaf(xk, w.x, o[4*m4+0]);
            o[4*m4+1] = fmaf(xk, w.y, o[4*m4+1]);
            o[4*m4+2] = fmaf(xk, w.z, o[4*m4+2]);
            o[4*m4+3] = fmaf(xk, w.w, o[4*m4+3]);
        }
    }

    int b = row >> 9;
    int s = row & 511;
    float* out = g_memT + (size_t)b * (MM * SS) + s;
    #pragma unroll
    for (int m = 0; m < 16; m++) out[m * SS] = o[m];   // coalesced per m
}

// ---------------------------------------------------------------------------
// Kernel 2: per-batch recurrent attention (5 steps) + write MLP + empty select
// One CTA of 256 threads per batch element. Static smem only (<48KB).
// Small GEMV weights live in per-thread registers:
//   whh row j      -> thread j        (j in [0,128))
//   proj_w row m   -> thread 128+m    (m in [0,16))
//   w_w1 row j     -> thread 144+j    (j in [0,32))
//   w_w2 row j     -> thread 176+j    (j in [0,32))
//   w_w3 row j     -> thread 192+j    (j in [0,64))
//   LSTM c state   -> register of thread tid (tid in [0,32))
// ---------------------------------------------------------------------------
__device__ __forceinline__ float sigmoidf_(float x) {
    return 1.f / (1.f + __expf(-x));
}

__global__ void __launch_bounds__(256) step_kernel(
    const int*   __restrict__ lengths,
    const float* __restrict__ whh,   // (128,32)
    const float* __restrict__ bih,   // 128
    const float* __restrict__ bhh,   // 128
    const float* __restrict__ pw,    // (16,32)
    const float* __restrict__ pb_,   // 16
    const float* __restrict__ w1,    // (32,32)
    const float* __restrict__ b1,    // 32
    const float* __restrict__ w2,    // (32,32)
    const float* __restrict__ b2,    // 32
    const float* __restrict__ w3,    // (64,32)
    const float* __restrict__ b3,    // 64
    const float* __restrict__ esv_,  // 64
    float*       __restrict__ out)   // (B,64)
{
    __shared__ float memT[MM * SS];   // 32 KB  [m*512 + s]
    __shared__ float qst[32];         // [0:16)=q, [16:32)=r
    __shared__ float gates[128];
    __shared__ float hst[32];
    __shared__ float red[128];
    __shared__ float scal[2];

    int b    = blockIdx.x;
    int tid  = threadIdx.x;
    int lane = tid & 31;
    int warp = tid >> 5;

    // ---- per-thread register weights ----
    float wr[32];                     // primary weight row
    float wr2[32];                    // secondary (only threads 192..207 use both w2 and w3)
    float bias0 = 0.f, bias1 = 0.f, esvr = 0.f;

    if (tid < 128) {
        #pragma unroll
        for (int k = 0; k < 32; k++) wr[k] = whh[tid * 32 + k];
        bias0 = bih[tid] + bhh[tid];
    } else if (tid < 144) {
        int m = tid - 128;
        #pragma unroll
        for (int k = 0; k < 32; k++) wr[k] = pw[m * 32 + k];
        bias0 = pb_[m];
    } else if (tid < 176) {
        int j = tid - 144;
        #pragma unroll
        for (int k = 0; k < 32; k++) wr[k] = w1[j * 32 + k];
        bias0 = b1[j];
    } else if (tid < 192) {
        int j = tid - 176;
        #pragma unroll
        for (int k = 0; k < 32; k++) wr[k] = w2[j * 32 + k];
        bias0 = b2[j];
    }
    if (tid >= 192 && tid < 208) {
        int j = tid - 176;            // w2 rows 16..31
        #pragma unroll
        for (int k = 0; k < 32; k++) wr[k] = w2[j * 32 + k];
        bias0 = b2[j];
    }
    if (tid >= 192) {
        int j = tid - 192;            // w3 rows 0..63
        #pragma unroll
        for (int k = 0; k < 32; k++) wr2[k] = w3[j * 32 + k];
        bias1 = b3[j];
        esvr  = esv_[j];
    }

    // ---- load memory tile (already transposed in global) ----
    {
        const float4* gm = (const float4*)(g_memT + (size_t)b * (MM * SS));
        float4* dst = (float4*)memT;
        #pragma unroll
        for (int i = tid; i < 2048; i += 256) dst[i] = gm[i];
    }
    float creg = 0.f;                 // LSTM c state for tid<32
    if (tid < 32) qst[tid] = 0.f;

    int len  = lengths[b];
    int slen = (len > 0) ? len : 1;
    __syncthreads();

    for (int step = 0; step < NSTEPS; step++) {
        // gates = q_star @ whh.T + bih + bhh   (threads 0..127)
        if (tid < 128) {
            float acc = bias0;
            #pragma unroll
            for (int k = 0; k < 32; k++) acc = fmaf(qst[k], wr[k], acc);
            gates[tid] = acc;
        }
        __syncthreads();
        // LSTM elementwise (threads 0..31), c in register
        if (tid < 32) {
            float ig = sigmoidf_(gates[tid]);
            float fg = sigmoidf_(gates[32 + tid]);
            float gg = tanhf(gates[64 + tid]);
            float og = sigmoidf_(gates[96 + tid]);
            creg = fmaf(fg, creg, ig * gg);
            hst[tid] = og * tanhf(creg);
        }
        __syncthreads();
        // q = h @ proj_w.T + proj_b  (threads 128..143)
        if (tid >= 128 && tid < 144) {
            float acc = bias0;
            #pragma unroll
            for (int k = 0; k < 32; k++) acc = fmaf(hst[k], wr[k], acc);
            qst[tid - 128] = acc;
        }
        __syncthreads();

        // e[s] = memT[:,s] . q  (thread handles s=tid, s=tid+256)
        float e0 = 0.f, e1 = 0.f;
        #pragma unroll
        for (int m = 0; m < 16; m++) {
            float qm = qst[m];
            e0 = fmaf(memT[m*512 + tid],       qm, e0);
            e1 = fmaf(memT[m*512 + tid + 256], qm, e1);
        }
        if (tid       >= slen) e0 = -1e30f;
        if (tid + 256 >= slen) e1 = -1e30f;

        // softmax max
        float mx = fmaxf(e0, e1);
        #pragma unroll
        for (int off = 16; off; off >>= 1)
            mx = fmaxf(mx, __shfl_xor_sync(0xffffffffu, mx, off));
        if (lane == 0) red[warp] = mx;
        __syncthreads();
        if (tid == 0) {
            float m = red[0];
            #pragma unroll
            for (int w = 1; w < 8; w++) m = fmaxf(m, red[w]);
            scal[0] = m;
        }
        __syncthreads();
        mx = scal[0];

        float ex0 = __expf(e0 - mx);
        float ex1 = __expf(e1 - mx);
        float s2  = ex0 + ex1;
        #pragma unroll
        for (int off = 16; off; off >>= 1)
            s2 += __shfl_xor_sync(0xffffffffu, s2, off);
        if (lane == 0) red[warp] = s2;
        __syncthreads();
        if (tid == 0) {
            float s = 0.f;
            #pragma unroll
            for (int w = 0; w < 8; w++) s += red[w];
            scal[1] = s;
        }
        __syncthreads();
        float inv = 1.f / scal[1];

        // r[m] = (1/Z) * sum_s exp(e)* memT[m][s]
        float rl[16];
        #pragma unroll
        for (int m = 0; m < 16; m++)
            rl[m] = fmaf(memT[m*512 + tid], ex0, memT[m*512 + tid + 256] * ex1);
        #pragma unroll
        for (int m = 0; m < 16; m++) {
            #pragma unroll
            for (int off = 16; off; off >>= 1)
                rl[m] += __shfl_xor_sync(0xffffffffu, rl[m], off);
        }
        if (lane == 0) {
            #pragma unroll
            for (int m = 0; m < 16; m++) red[warp*16 + m] = rl[m];
        }
        __syncthreads();
        if (tid < 16) {
            float acc = 0.f;
            #pragma unroll
            for (int w = 0; w < 8; w++) acc += red[w*16 + tid];
            qst[16 + tid] = acc * inv;
        }
        __syncthreads();
    }

    // ---- write MLP: 32 -> 32 relu -> 32 relu -> 64 ----
    if (tid >= 144 && tid < 176) {           // layer 1
        float acc = bias0;
        #pragma unroll
        for (int k = 0; k < 32; k++) acc = fmaf(qst[k], wr[k], acc);
        red[tid - 144] = fmaxf(acc, 0.f);
    }
    __syncthreads();
    if (tid >= 176 && tid < 208) {           // layer 2
        float acc = bias0;
        #pragma unroll
        for (int k = 0; k < 32; k++) acc = fmaf(red[k], wr[k], acc);
        red[32 + (tid - 176)] = fmaxf(acc, 0.f);
    }
    __syncthreads();
    if (tid >= 192) {                        // layer 3 + empty-set select
        float acc = bias1;
        #pragma unroll
        for (int k = 0; k < 32; k++) acc = fmaf(red[32 + k], wr2[k], acc);
        out[(size_t)b * OUTD + (tid - 192)] = (len > 0) ? acc : esvr;
    }
}

// ---------------------------------------------------------------------------
extern "C" void kernel_launch(void* const* d_in, const int* in_sizes, int n_in,
                              void* d_out, int out_size)
{
    const float* input_set = (const float*)d_in[0];
    const int*   lengths   = (const int*)  d_in[1];
    const float* r_w1 = (const float*)d_in[2];
    const float* r_b1 = (const float*)d_in[3];
    const float* r_w2 = (const float*)d_in[4];
    const float* r_b2 = (const float*)d_in[5];
    const float* r_w3 = (const float*)d_in[6];
    const float* r_b3 = (const float*)d_in[7];
    // d_in[8] = lstm_wih (unused: LSTM input is identically zero)
    const float* lstm_whh = (const float*)d_in[9];
    const float* lstm_bih = (const float*)d_in[10];
    const float* lstm_bhh = (const float*)d_in[11];
    const float* proj_w   = (const float*)d_in[12];
    const float* proj_b   = (const float*)d_in[13];
    const float* w_w1 = (const float*)d_in[14];
    const float* w_b1 = (const float*)d_in[15];
    const float* w_w2 = (const float*)d_in[16];
    const float* w_b2 = (const float*)d_in[17];
    const float* w_w3 = (const float*)d_in[18];
    const float* w_b3 = (const float*)d_in[19];
    const float* esv  = (const float*)d_in[20];
    float* out = (float*)d_out;

    mem_mlp_kernel<<<(BB * SS) / 256, 256>>>(input_set,
                                             r_w1, r_b1, r_w2, r_b2, r_w3, r_b3);

    step_kernel<<<BB, 256>>>(lengths,
                             lstm_whh, lstm_bih, lstm_bhh,
                             proj_w, proj_b,
                             w_w1, w_b1, w_w2, w_b2, w_w3, w_b3,
                             esv, out);
}

// round 4
// speedup vs baseline: 1.1890x; 1.1890x over previous
#include <cuda_runtime.h>
#include <cuda_bf16.h>
#include <math.h>

#define BB 4096
#define SS 512
#define EE 64
#define MM 16
#define OUTD 64
#define NSTEPS 5

// Scratch: memories transposed per batch: g_memT[b*MM*SS + m*SS + s]
__device__ float g_memT[(size_t)BB * MM * SS];
// Pre-transposed small weights (k-major) for the recurrence kernel
__device__ float g_whhT[32 * 128];   // [k][j]
__device__ float g_pwT [32 * 16];    // [k][m]
__device__ float g_w1T [32 * 32];    // [k][j]
__device__ float g_w2T [32 * 32];    // [k][j]
__device__ float g_w3T [32 * 64];    // [k][j]
__device__ float g_bsum[128];        // bih + bhh

// ---------------- packed fp32x2 helpers (sm_103a FFMA2) ----------------
#define PACK2(out, lo, hi) \
    asm("mov.b64 %0, {%1, %2};" : "=l"(out) : "r"(__float_as_uint(lo)), "r"(__float_as_uint(hi)))
#define UNPACK2(lo, hi, in) \
    do { unsigned int _a, _b; \
         asm("mov.b64 {%0, %1}, %2;" : "=r"(_a), "=r"(_b) : "l"(in)); \
         lo = __uint_as_float(_a); hi = __uint_as_float(_b); } while (0)
#define FMA2(acc, a, b) \
    asm("fma.rn.f32x2 %0, %1, %2, %0;" : "+l"(acc) : "l"(a), "l"(b))

// ---------------------------------------------------------------------------
// Kernel 0: one-time weight transposes into global scratch
// ---------------------------------------------------------------------------
__global__ void prep_kernel(
    const float* __restrict__ whh, const float* __restrict__ bih,
    const float* __restrict__ bhh, const float* __restrict__ pw,
    const float* __restrict__ w1,  const float* __restrict__ w2,
    const float* __restrict__ w3)
{
    int tid = threadIdx.x;
    for (int i = tid; i < 4096; i += 256) { int j = i >> 5, k = i & 31; g_whhT[k*128 + j] = whh[i]; }
    for (int i = tid; i < 512;  i += 256) { int m = i >> 5, k = i & 31; g_pwT [k*16  + m] = pw[i]; }
    for (int i = tid; i < 1024; i += 256) { int j = i >> 5, k = i & 31; g_w1T[k*32 + j] = w1[i];
                                            g_w2T[k*32 + j] = w2[i]; }
    for (int i = tid; i < 2048; i += 256) { int j = i >> 5, k = i & 31; g_w3T[k*64 + j] = w3[i]; }
    if (tid < 128) g_bsum[tid] = bih[tid] + bhh[tid];
}

// ---------------------------------------------------------------------------
// Kernel 1: memories = MLP(input_set)  64 -> 32 -> 32 -> 16 (relu,relu,lin)
// One thread per row; accumulators packed as f32x2 -> FFMA2 halves fma load.
// Weights in smem, broadcast wide LDS.
// ---------------------------------------------------------------------------
__global__ void __launch_bounds__(256) mem_mlp_kernel(
    const float* __restrict__ x,
    const float* __restrict__ w1, const float* __restrict__ b1,
    const float* __restrict__ w2, const float* __restrict__ b2,
    const float* __restrict__ w3, const float* __restrict__ b3)
{
    __shared__ __align__(16) float sw1T[64 * 32];   // [k][j]
    __shared__ __align__(16) float sw2T[32 * 32];   // [k][j]
    __shared__ __align__(16) float sw3T[32 * 16];   // [k][m]
    __shared__ __align__(16) float sb1[32];
    __shared__ __align__(16) float sb2[32];
    __shared__ __align__(16) float sb3[16];

    int tid = threadIdx.x;
    for (int i = tid; i < 2048; i += 256) { int j = i >> 6, k = i & 63; sw1T[k*32 + j] = w1[i]; }
    for (int i = tid; i < 1024; i += 256) { int j = i >> 5, k = i & 31; sw2T[k*32 + j] = w2[i]; }
    for (int i = tid; i < 512;  i += 256) { int m = i >> 5, k = i & 31; sw3T[k*16 + m] = w3[i]; }
    if (tid < 32) { sb1[tid] = b1[tid]; sb2[tid] = b2[tid]; }
    if (tid < 16) sb3[tid] = b3[tid];
    __syncthreads();

    int row = blockIdx.x * 256 + tid;          // exact grid
    const float4* xv = (const float4*)(x + (size_t)row * EE);

    // ---- layer 1: 64 -> 32, relu ----
    unsigned long long acc[16];
    {
        const unsigned long long* bp = (const unsigned long long*)sb1;
        #pragma unroll
        for (int p = 0; p < 16; p++) acc[p] = bp[p];
    }
    #pragma unroll
    for (int k4 = 0; k4 < 16; k4++) {
        float4 xc = xv[k4];
        #pragma unroll
        for (int kk = 0; kk < 4; kk++) {
            float xk = (kk == 0) ? xc.x : (kk == 1) ? xc.y : (kk == 2) ? xc.z : xc.w;
            unsigned long long xp; PACK2(xp, xk, xk);
            const ulonglong2* wv = (const ulonglong2*)(sw1T + (k4*4 + kk) * 32);
            #pragma unroll
            for (int p = 0; p < 8; p++) {
                ulonglong2 w = wv[p];
                FMA2(acc[2*p+0], xp, w.x);
                FMA2(acc[2*p+1], xp, w.y);
            }
        }
    }
    float h1[32];
    #pragma unroll
    for (int p = 0; p < 16; p++) {
        float lo, hi; UNPACK2(lo, hi, acc[p]);
        h1[2*p] = fmaxf(lo, 0.f); h1[2*p+1] = fmaxf(hi, 0.f);
    }

    // ---- layer 2: 32 -> 32, relu ----
    {
        const unsigned long long* bp = (const unsigned long long*)sb2;
        #pragma unroll
        for (int p = 0; p < 16; p++) acc[p] = bp[p];
    }
    #pragma unroll
    for (int k = 0; k < 32; k++) {
        unsigned long long xp; PACK2(xp, h1[k], h1[k]);
        const ulonglong2* wv = (const ulonglong2*)(sw2T + k * 32);
        #pragma unroll
        for (int p = 0; p < 8; p++) {
            ulonglong2 w = wv[p];
            FMA2(acc[2*p+0], xp, w.x);
            FMA2(acc[2*p+1], xp, w.y);
        }
    }
    float h2[32];
    #pragma unroll
    for (int p = 0; p < 16; p++) {
        float lo, hi; UNPACK2(lo, hi, acc[p]);
        h2[2*p] = fmaxf(lo, 0.f); h2[2*p+1] = fmaxf(hi, 0.f);
    }

    // ---- layer 3: 32 -> 16, linear ----
    unsigned long long acc3[8];
    {
        const unsigned long long* bp = (const unsigned long long*)sb3;
        #pragma unroll
        for (int p = 0; p < 8; p++) acc3[p] = bp[p];
    }
    #pragma unroll
    for (int k = 0; k < 32; k++) {
        unsigned long long xp; PACK2(xp, h2[k], h2[k]);
        const ulonglong2* wv = (const ulonglong2*)(sw3T + k * 16);
        #pragma unroll
        for (int p = 0; p < 4; p++) {
            ulonglong2 w = wv[p];
            FMA2(acc3[2*p+0], xp, w.x);
            FMA2(acc3[2*p+1], xp, w.y);
        }
    }

    int b = row >> 9;
    int s = row & 511;
    float* out = g_memT + (size_t)b * (MM * SS) + s;
    #pragma unroll
    for (int p = 0; p < 8; p++) {
        float lo, hi; UNPACK2(lo, hi, acc3[p]);
        out[(2*p)   * SS] = lo;
        out[(2*p+1) * SS] = hi;
    }
}

// ---------------------------------------------------------------------------
// Kernel 2: ONE WARP PER BATCH. Zero block barriers: all reductions via
// shuffles. State distributed one element per lane. memT tile in 32KB smem.
// ---------------------------------------------------------------------------
__device__ __forceinline__ float sigmoidf_(float x) {
    return 1.f / (1.f + __expf(-x));
}

__global__ void __launch_bounds__(32) step_kernel(
    const int*   __restrict__ lengths,
    const float* __restrict__ pb_,   // 16
    const float* __restrict__ b1,    // 32
    const float* __restrict__ b2,    // 32
    const float* __restrict__ b3,    // 64
    const float* __restrict__ esv_,  // 64
    float*       __restrict__ out)   // (B,64)
{
    __shared__ __align__(16) float memT[MM * SS];   // 32 KB [m*512 + s]

    const unsigned FULL = 0xffffffffu;
    int b    = blockIdx.x;
    int lane = threadIdx.x;

    // preload per-lane biases / rows
    float bs0 = g_bsum[lane];
    float bs1 = g_bsum[32 + lane];
    float bs2 = g_bsum[64 + lane];
    float bs3 = g_bsum[96 + lane];
    float pbr = pb_[lane & 15];
    float b1r = b1[lane];
    float b2r = b2[lane];
    float b3r0 = b3[lane],  b3r1 = b3[32 + lane];
    float ev0  = esv_[lane], ev1 = esv_[32 + lane];

    // load the memory tile (2048 float4, 64 per lane)
    {
        const float4* gm = (const float4*)(g_memT + (size_t)b * (MM * SS));
        float4* dst = (float4*)memT;
        #pragma unroll
        for (int i = lane; i < 2048; i += 32) dst[i] = gm[i];
    }
    int len  = lengths[b];
    int slen = (len > 0) ? len : 1;
    __syncwarp();

    float qstar = 0.f;      // q_star[lane]
    float c     = 0.f;      // LSTM cell state[lane]

    #pragma unroll 1
    for (int step = 0; step < NSTEPS; step++) {
        // ---- gates = q_star @ whh.T + (bih+bhh); lane computes 4 gates ----
        float a0 = bs0, a1 = bs1, a2 = bs2, a3 = bs3;
        #pragma unroll
        for (int k = 0; k < 32; k++) {
            float qk = __shfl_sync(FULL, qstar, k);
            const float* wr = g_whhT + k * 128;
            a0 = fmaf(qk, __ldg(wr + lane),       a0);
            a1 = fmaf(qk, __ldg(wr + 32 + lane),  a1);
            a2 = fmaf(qk, __ldg(wr + 64 + lane),  a2);
            a3 = fmaf(qk, __ldg(wr + 96 + lane),  a3);
        }
        // ---- LSTM elementwise ----
        float ig = sigmoidf_(a0);
        float fg = sigmoidf_(a1);
        float gg = tanhf(a2);
        float og = sigmoidf_(a3);
        c = fmaf(fg, c, ig * gg);
        float h = og * tanhf(c);

        // ---- q = h @ proj_w.T + proj_b (meaningful for lane<16) ----
        float aq = pbr;
        {
            int m = lane & 15;
            #pragma unroll
            for (int k = 0; k < 32; k++) {
                float hk = __shfl_sync(FULL, h, k);
                aq = fmaf(hk, __ldg(g_pwT + k * 16 + m), aq);
            }
        }
        // materialize q[0..15] in every lane
        float qm[16];
        #pragma unroll
        for (int m = 0; m < 16; m++) qm[m] = __shfl_sync(FULL, aq, m);

        // ---- e[s] = memT[:,s].q, masked; lane handles s = lane + 32t ----
        float e[16];
        #pragma unroll
        for (int t = 0; t < 16; t++) {
            int s = lane + 32 * t;
            float acc = 0.f;
            #pragma unroll
            for (int m = 0; m < 16; m++)
                acc = fmaf(qm[m], memT[m * 512 + s], acc);
            e[t] = (s < slen) ? acc : -1e30f;
        }
        // softmax (warp-wide)
        float mx = e[0];
        #pragma unroll
        for (int t = 1; t < 16; t++) mx = fmaxf(mx, e[t]);
        #pragma unroll
        for (int off = 16; off; off >>= 1)
            mx = fmaxf(mx, __shfl_xor_sync(FULL, mx, off));
        float ex[16]; float ssum = 0.f;
        #pragma unroll
        for (int t = 0; t < 16; t++) { ex[t] = __expf(e[t] - mx); ssum += ex[t]; }
        #pragma unroll
        for (int off = 16; off; off >>= 1)
            ssum += __shfl_xor_sync(FULL, ssum, off);
        float inv = 1.f / ssum;

        // ---- r[m] = sum_s a[s] memT[m][s] ----
        float rm[16];
        #pragma unroll
        for (int m = 0; m < 16; m++) rm[m] = 0.f;
        #pragma unroll
        for (int t = 0; t < 16; t++) {
            int s = lane + 32 * t;
            float w = ex[t];
            #pragma unroll
            for (int m = 0; m < 16; m++)
                rm[m] = fmaf(w, memT[m * 512 + s], rm[m]);
        }
        #pragma unroll
        for (int m = 0; m < 16; m++) {
            #pragma unroll
            for (int off = 16; off; off >>= 1)
                rm[m] += __shfl_xor_sync(FULL, rm[m], off);
        }

        // ---- q_star = concat(q, r) distributed one per lane ----
        float nq = 0.f;
        #pragma unroll
        for (int m = 0; m < 16; m++) nq = (lane == m)      ? qm[m]        : nq;
        #pragma unroll
        for (int m = 0; m < 16; m++) nq = (lane == 16 + m) ? rm[m] * inv  : nq;
        qstar = nq;
    }

    // ---- write MLP: 32 -> 32 relu -> 32 relu -> 64 ----
    float x1 = b1r;
    #pragma unroll
    for (int k = 0; k < 32; k++) {
        float qk = __shfl_sync(FULL, qstar, k);
        x1 = fmaf(qk, __ldg(g_w1T + k * 32 + lane), x1);
    }
    x1 = fmaxf(x1, 0.f);

    float x2 = b2r;
    #pragma unroll
    for (int k = 0; k < 32; k++) {
        float hk = __shfl_sync(FULL, x1, k);
        x2 = fmaf(hk, __ldg(g_w2T + k * 32 + lane), x2);
    }
    x2 = fmaxf(x2, 0.f);

    float o0 = b3r0, o1 = b3r1;
    #pragma unroll
    for (int k = 0; k < 32; k++) {
        float hk = __shfl_sync(FULL, x2, k);
        o0 = fmaf(hk, __ldg(g_w3T + k * 64 + lane),      o0);
        o1 = fmaf(hk, __ldg(g_w3T + k * 64 + 32 + lane), o1);
    }
    float* op = out + (size_t)b * OUTD;
    op[lane]      = (len > 0) ? o0 : ev0;
    op[32 + lane] = (len > 0) ? o1 : ev1;
}

// ---------------------------------------------------------------------------
extern "C" void kernel_launch(void* const* d_in, const int* in_sizes, int n_in,
                              void* d_out, int out_size)
{
    const float* input_set = (const float*)d_in[0];
    const int*   lengths   = (const int*)  d_in[1];
    const float* r_w1 = (const float*)d_in[2];
    const float* r_b1 = (const float*)d_in[3];
    const float* r_w2 = (const float*)d_in[4];
    const float* r_b2 = (const float*)d_in[5];
    const float* r_w3 = (const float*)d_in[6];
    const float* r_b3 = (const float*)d_in[7];
    // d_in[8] = lstm_wih (unused: LSTM input is identically zero)
    const float* lstm_whh = (const float*)d_in[9];
    const float* lstm_bih = (const float*)d_in[10];
    const float* lstm_bhh = (const float*)d_in[11];
    const float* proj_w   = (const float*)d_in[12];
    const float* proj_b   = (const float*)d_in[13];
    const float* w_w1 = (const float*)d_in[14];
    const float* w_b1 = (const float*)d_in[15];
    const float* w_w2 = (const float*)d_in[16];
    const float* w_b2 = (const float*)d_in[17];
    const float* w_w3 = (const float*)d_in[18];
    const float* w_b3 = (const float*)d_in[19];
    const float* esv  = (const float*)d_in[20];
    float* out = (float*)d_out;

    prep_kernel<<<1, 256>>>(lstm_whh, lstm_bih, lstm_bhh, proj_w,
                            w_w1, w_w2, w_w3);

    mem_mlp_kernel<<<(BB * SS) / 256, 256>>>(input_set,
                                             r_w1, r_b1, r_w2, r_b2, r_w3, r_b3);

    step_kernel<<<BB, 32>>>(lengths, proj_b, w_b1, w_b2, w_b3, esv, out);
}

// round 5
// speedup vs baseline: 1.5754x; 1.3249x over previous
#include <cuda_runtime.h>
#include <cuda_bf16.h>
#include <math.h>

#define BB 4096
#define SS 512
#define EE 64
#define MM 16
#define OUTD 64
#define NSTEPS 5

// Scratch: memories transposed per batch: g_memT[b*MM*SS + m*SS + s]
__device__ float g_memT[(size_t)BB * MM * SS];
// Pre-transposed small weights (k-major) for the recurrence kernel
__device__ float g_whhT[32 * 128];   // [k][j]
__device__ float g_pwT [32 * 16];    // [k][m]
__device__ float g_w1T [32 * 32];    // [k][j]
__device__ float g_w2T [32 * 32];    // [k][j]
__device__ float g_w3T [32 * 64];    // [k][j]
__device__ float g_bsum[128];        // bih + bhh

// ---------------- packed fp32x2 helpers (sm_103a FFMA2) ----------------
#define PACK2(out, lo, hi) \
    asm("mov.b64 %0, {%1, %2};" : "=l"(out) : "r"(__float_as_uint(lo)), "r"(__float_as_uint(hi)))
#define UNPACK2(lo, hi, in) \
    do { unsigned int _a, _b; \
         asm("mov.b64 {%0, %1}, %2;" : "=r"(_a), "=r"(_b) : "l"(in)); \
         lo = __uint_as_float(_a); hi = __uint_as_float(_b); } while (0)
#define FMA2(acc, a, b) \
    asm("fma.rn.f32x2 %0, %1, %2, %0;" : "+l"(acc) : "l"(a), "l"(b))

// ---------------------------------------------------------------------------
// Kernel 0: one-time weight transposes (wide grid -> a few us, not 19)
// ---------------------------------------------------------------------------
__global__ void prep_kernel(
    const float* __restrict__ whh, const float* __restrict__ bih,
    const float* __restrict__ bhh, const float* __restrict__ pw,
    const float* __restrict__ w1,  const float* __restrict__ w2,
    const float* __restrict__ w3)
{
    int gid = blockIdx.x * 128 + threadIdx.x;   // 4096 threads
    int nt  = gridDim.x * 128;
    for (int i = gid; i < 4096; i += nt) { int j = i >> 5, k = i & 31; g_whhT[k*128 + j] = whh[i]; }
    for (int i = gid; i < 512;  i += nt) { int m = i >> 5, k = i & 31; g_pwT [k*16  + m] = pw[i]; }
    for (int i = gid; i < 1024; i += nt) { int j = i >> 5, k = i & 31; g_w1T[k*32 + j] = w1[i];
                                           g_w2T[k*32 + j] = w2[i]; }
    for (int i = gid; i < 2048; i += nt) { int j = i >> 5, k = i & 31; g_w3T[k*64 + j] = w3[i]; }
    if (gid < 128) g_bsum[gid] = bih[gid] + bhh[gid];
}

// ---------------------------------------------------------------------------
// Kernel 1: memories = MLP(input_set)  64 -> 32 -> 32 -> 16 (relu,relu,lin)
// Block = one batch element (512 rows); thread t handles rows (t, t+256),
// sharing each weight LDS across both rows -> FFMA2:LDS issue ratio 4:1.
// ---------------------------------------------------------------------------
__global__ void __launch_bounds__(256) mem_mlp_kernel(
    const float* __restrict__ x,
    const float* __restrict__ w1, const float* __restrict__ b1,
    const float* __restrict__ w2, const float* __restrict__ b2,
    const float* __restrict__ w3, const float* __restrict__ b3)
{
    __shared__ __align__(16) float sw1T[64 * 32];   // [k][j]
    __shared__ __align__(16) float sw2T[32 * 32];   // [k][j]
    __shared__ __align__(16) float sw3T[32 * 16];   // [k][m]
    __shared__ __align__(16) float sb1[32];
    __shared__ __align__(16) float sb2[32];
    __shared__ __align__(16) float sb3[16];

    int tid = threadIdx.x;
    for (int i = tid; i < 2048; i += 256) { int j = i >> 6, k = i & 63; sw1T[k*32 + j] = w1[i]; }
    for (int i = tid; i < 1024; i += 256) { int j = i >> 5, k = i & 31; sw2T[k*32 + j] = w2[i]; }
    for (int i = tid; i < 512;  i += 256) { int m = i >> 5, k = i & 31; sw3T[k*16 + m] = w3[i]; }
    if (tid < 32) { sb1[tid] = b1[tid]; sb2[tid] = b2[tid]; }
    if (tid < 16) sb3[tid] = b3[tid];
    __syncthreads();

    int b  = blockIdx.x;
    int s0 = tid;            // row A: s = tid
    int s1 = tid + 256;      // row B: s = tid + 256
    const float4* xv0 = (const float4*)(x + ((size_t)b * SS + s0) * EE);
    const float4* xv1 = (const float4*)(x + ((size_t)b * SS + s1) * EE);

    // ---- layer 1: 64 -> 32, relu ----
    unsigned long long a0[16], a1[16];
    {
        const unsigned long long* bp = (const unsigned long long*)sb1;
        #pragma unroll
        for (int p = 0; p < 16; p++) { a0[p] = bp[p]; a1[p] = bp[p]; }
    }
    #pragma unroll
    for (int k4 = 0; k4 < 16; k4++) {
        float4 xc0 = xv0[k4];
        float4 xc1 = xv1[k4];
        #pragma unroll
        for (int kk = 0; kk < 4; kk++) {
            float f0 = (kk==0)?xc0.x:(kk==1)?xc0.y:(kk==2)?xc0.z:xc0.w;
            float f1 = (kk==0)?xc1.x:(kk==1)?xc1.y:(kk==2)?xc1.z:xc1.w;
            unsigned long long xp0, xp1;
            PACK2(xp0, f0, f0);
            PACK2(xp1, f1, f1);
            const ulonglong2* wv = (const ulonglong2*)(sw1T + (k4*4 + kk) * 32);
            #pragma unroll
            for (int p = 0; p < 8; p++) {
                ulonglong2 w = wv[p];
                FMA2(a0[2*p+0], xp0, w.x);
                FMA2(a0[2*p+1], xp0, w.y);
                FMA2(a1[2*p+0], xp1, w.x);
                FMA2(a1[2*p+1], xp1, w.y);
            }
        }
    }
    float h0[32], h1[32];
    #pragma unroll
    for (int p = 0; p < 16; p++) {
        float lo, hi;
        UNPACK2(lo, hi, a0[p]); h0[2*p] = fmaxf(lo, 0.f); h0[2*p+1] = fmaxf(hi, 0.f);
        UNPACK2(lo, hi, a1[p]); h1[2*p] = fmaxf(lo, 0.f); h1[2*p+1] = fmaxf(hi, 0.f);
    }

    // ---- layer 2: 32 -> 32, relu ----
    {
        const unsigned long long* bp = (const unsigned long long*)sb2;
        #pragma unroll
        for (int p = 0; p < 16; p++) { a0[p] = bp[p]; a1[p] = bp[p]; }
    }
    #pragma unroll
    for (int k = 0; k < 32; k++) {
        unsigned long long xp0, xp1;
        PACK2(xp0, h0[k], h0[k]);
        PACK2(xp1, h1[k], h1[k]);
        const ulonglong2* wv = (const ulonglong2*)(sw2T + k * 32);
        #pragma unroll
        for (int p = 0; p < 8; p++) {
            ulonglong2 w = wv[p];
            FMA2(a0[2*p+0], xp0, w.x);
            FMA2(a0[2*p+1], xp0, w.y);
            FMA2(a1[2*p+0], xp1, w.x);
            FMA2(a1[2*p+1], xp1, w.y);
        }
    }
    #pragma unroll
    for (int p = 0; p < 16; p++) {
        float lo, hi;
        UNPACK2(lo, hi, a0[p]); h0[2*p] = fmaxf(lo, 0.f); h0[2*p+1] = fmaxf(hi, 0.f);
        UNPACK2(lo, hi, a1[p]); h1[2*p] = fmaxf(lo, 0.f); h1[2*p+1] = fmaxf(hi, 0.f);
    }

    // ---- layer 3: 32 -> 16, linear ----
    unsigned long long c0[8], c1[8];
    {
        const unsigned long long* bp = (const unsigned long long*)sb3;
        #pragma unroll
        for (int p = 0; p < 8; p++) { c0[p] = bp[p]; c1[p] = bp[p]; }
    }
    #pragma unroll
    for (int k = 0; k < 32; k++) {
        unsigned long long xp0, xp1;
        PACK2(xp0, h0[k], h0[k]);
        PACK2(xp1, h1[k], h1[k]);
        const ulonglong2* wv = (const ulonglong2*)(sw3T + k * 16);
        #pragma unroll
        for (int p = 0; p < 4; p++) {
            ulonglong2 w = wv[p];
            FMA2(c0[2*p+0], xp0, w.x);
            FMA2(c0[2*p+1], xp0, w.y);
            FMA2(c1[2*p+0], xp1, w.x);
            FMA2(c1[2*p+1], xp1, w.y);
        }
    }

    float* outb = g_memT + (size_t)b * (MM * SS);
    #pragma unroll
    for (int p = 0; p < 8; p++) {
        float lo, hi;
        UNPACK2(lo, hi, c0[p]);
        outb[(2*p) * SS + s0] = lo; outb[(2*p+1) * SS + s0] = hi;
        UNPACK2(lo, hi, c1[p]);
        outb[(2*p) * SS + s1] = lo; outb[(2*p+1) * SS + s1] = hi;
    }
}

// ---------------------------------------------------------------------------
// Kernel 2: ONE WARP PER BATCH, attention loops fully vectorized:
// lane owns s = 4*lane + 128*t (t=0..3) -> all memT traffic is conflict-free
// LDS.128 (consecutive lanes -> consecutive 16B).
// ---------------------------------------------------------------------------
__device__ __forceinline__ float sigmoidf_(float x) {
    return 1.f / (1.f + __expf(-x));
}

__global__ void __launch_bounds__(32) step_kernel(
    const int*   __restrict__ lengths,
    const float* __restrict__ pb_,   // 16
    const float* __restrict__ b1,    // 32
    const float* __restrict__ b2,    // 32
    const float* __restrict__ b3,    // 64
    const float* __restrict__ esv_,  // 64
    float*       __restrict__ out)   // (B,64)
{
    __shared__ __align__(16) float memT[MM * SS];   // 32 KB [m*512 + s]

    const unsigned FULL = 0xffffffffu;
    int b    = blockIdx.x;
    int lane = threadIdx.x;

    // per-lane biases
    float bs0 = g_bsum[lane];
    float bs1 = g_bsum[32 + lane];
    float bs2 = g_bsum[64 + lane];
    float bs3 = g_bsum[96 + lane];
    float pbr = pb_[lane & 15];
    float b1r = b1[lane];
    float b2r = b2[lane];
    float b3r0 = b3[lane],  b3r1 = b3[32 + lane];
    float ev0  = esv_[lane], ev1 = esv_[32 + lane];

    // load the memory tile (2048 float4, 64 per lane, coalesced)
    {
        const float4* gm = (const float4*)(g_memT + (size_t)b * (MM * SS));
        float4* dst = (float4*)memT;
        #pragma unroll
        for (int i = lane; i < 2048; i += 32) dst[i] = gm[i];
    }
    int len  = lengths[b];
    int slen = (len > 0) ? len : 1;
    __syncwarp();

    const float4* memT4 = (const float4*)memT;   // index m*128 + (s/4)

    float qstar = 0.f;      // q_star[lane]
    float c     = 0.f;      // LSTM cell state[lane]

    #pragma unroll 1
    for (int step = 0; step < NSTEPS; step++) {
        // ---- gates = q_star @ whh.T + (bih+bhh); lane computes 4 gates ----
        float a0 = bs0, a1 = bs1, a2 = bs2, a3 = bs3;
        #pragma unroll
        for (int k = 0; k < 32; k++) {
            float qk = __shfl_sync(FULL, qstar, k);
            const float* wr = g_whhT + k * 128;
            a0 = fmaf(qk, __ldg(wr + lane),       a0);
            a1 = fmaf(qk, __ldg(wr + 32 + lane),  a1);
            a2 = fmaf(qk, __ldg(wr + 64 + lane),  a2);
            a3 = fmaf(qk, __ldg(wr + 96 + lane),  a3);
        }
        // ---- LSTM elementwise ----
        float ig = sigmoidf_(a0);
        float fg = sigmoidf_(a1);
        float gg = tanhf(a2);
        float og = sigmoidf_(a3);
        c = fmaf(fg, c, ig * gg);
        float h = og * tanhf(c);

        // ---- q = h @ proj_w.T + proj_b ----
        float aq = pbr;
        {
            int m = lane & 15;
            #pragma unroll
            for (int k = 0; k < 32; k++) {
                float hk = __shfl_sync(FULL, h, k);
                aq = fmaf(hk, __ldg(g_pwT + k * 16 + m), aq);
            }
        }
        float qm[16];
        #pragma unroll
        for (int m = 0; m < 16; m++) qm[m] = __shfl_sync(FULL, aq, m);

        // ---- e[s] = memT[:,s].q ; lane owns s = 4*lane + 128*t ----
        float4 ev[4];
        #pragma unroll
        for (int t = 0; t < 4; t++) {
            float4 acc = make_float4(0.f, 0.f, 0.f, 0.f);
            int base = lane + 32 * t;
            #pragma unroll
            for (int m = 0; m < 16; m++) {
                float4 v = memT4[m * 128 + base];
                float q = qm[m];
                acc.x = fmaf(q, v.x, acc.x);
                acc.y = fmaf(q, v.y, acc.y);
                acc.z = fmaf(q, v.z, acc.z);
                acc.w = fmaf(q, v.w, acc.w);
            }
            int s = 4 * lane + 128 * t;
            if (s     >= slen) acc.x = -1e30f;
            if (s + 1 >= slen) acc.y = -1e30f;
            if (s + 2 >= slen) acc.z = -1e30f;
            if (s + 3 >= slen) acc.w = -1e30f;
            ev[t] = acc;
        }
        // softmax
        float mx = -1e30f;
        #pragma unroll
        for (int t = 0; t < 4; t++) {
            mx = fmaxf(mx, fmaxf(fmaxf(ev[t].x, ev[t].y), fmaxf(ev[t].z, ev[t].w)));
        }
        #pragma unroll
        for (int off = 16; off; off >>= 1)
            mx = fmaxf(mx, __shfl_xor_sync(FULL, mx, off));

        float4 ex[4]; float ssum = 0.f;
        #pragma unroll
        for (int t = 0; t < 4; t++) {
            ex[t].x = __expf(ev[t].x - mx);
            ex[t].y = __expf(ev[t].y - mx);
            ex[t].z = __expf(ev[t].z - mx);
            ex[t].w = __expf(ev[t].w - mx);
            ssum += (ex[t].x + ex[t].y) + (ex[t].z + ex[t].w);
        }
        #pragma unroll
        for (int off = 16; off; off >>= 1)
            ssum += __shfl_xor_sync(FULL, ssum, off);
        float inv = 1.f / ssum;

        // ---- r[m] = sum_s a[s] * memT[m][s] ----
        float rm[16];
        #pragma unroll
        for (int m = 0; m < 16; m++) rm[m] = 0.f;
        #pragma unroll
        for (int t = 0; t < 4; t++) {
            int base = lane + 32 * t;
            float4 w = ex[t];
            #pragma unroll
            for (int m = 0; m < 16; m++) {
                float4 v = memT4[m * 128 + base];
                rm[m] = fmaf(w.x, v.x, fmaf(w.y, v.y, fmaf(w.z, v.z, fmaf(w.w, v.w, rm[m]))));
            }
        }
        #pragma unroll
        for (int m = 0; m < 16; m++) {
            #pragma unroll
            for (int off = 16; off; off >>= 1)
                rm[m] += __shfl_xor_sync(FULL, rm[m], off);
        }

        // ---- q_star = concat(q, r) distributed one per lane ----
        float nq = 0.f;
        #pragma unroll
        for (int m = 0; m < 16; m++) nq = (lane == m)      ? qm[m]        : nq;
        #pragma unroll
        for (int m = 0; m < 16; m++) nq = (lane == 16 + m) ? rm[m] * inv  : nq;
        qstar = nq;
    }

    // ---- write MLP: 32 -> 32 relu -> 32 relu -> 64 ----
    float x1 = b1r;
    #pragma unroll
    for (int k = 0; k < 32; k++) {
        float qk = __shfl_sync(FULL, qstar, k);
        x1 = fmaf(qk, __ldg(g_w1T + k * 32 + lane), x1);
    }
    x1 = fmaxf(x1, 0.f);

    float x2 = b2r;
    #pragma unroll
    for (int k = 0; k < 32; k++) {
        float hk = __shfl_sync(FULL, x1, k);
        x2 = fmaf(hk, __ldg(g_w2T + k * 32 + lane), x2);
    }
    x2 = fmaxf(x2, 0.f);

    float o0 = b3r0, o1 = b3r1;
    #pragma unroll
    for (int k = 0; k < 32; k++) {
        float hk = __shfl_sync(FULL, x2, k);
        o0 = fmaf(hk, __ldg(g_w3T + k * 64 + lane),      o0);
        o1 = fmaf(hk, __ldg(g_w3T + k * 64 + 32 + lane), o1);
    }
    float* op = out + (size_t)b * OUTD;
    op[lane]      = (len > 0) ? o0 : ev0;
    op[32 + lane] = (len > 0) ? o1 : ev1;
}

// ---------------------------------------------------------------------------
extern "C" void kernel_launch(void* const* d_in, const int* in_sizes, int n_in,
                              void* d_out, int out_size)
{
    const float* input_set = (const float*)d_in[0];
    const int*   lengths   = (const int*)  d_in[1];
    const float* r_w1 = (const float*)d_in[2];
    const float* r_b1 = (const float*)d_in[3];
    const float* r_w2 = (const float*)d_in[4];
    const float* r_b2 = (const float*)d_in[5];
    const float* r_w3 = (const float*)d_in[6];
    const float* r_b3 = (const float*)d_in[7];
    // d_in[8] = lstm_wih (unused: LSTM input is identically zero)
    const float* lstm_whh = (const float*)d_in[9];
    const float* lstm_bih = (const float*)d_in[10];
    const float* lstm_bhh = (const float*)d_in[11];
    const float* proj_w   = (const float*)d_in[12];
    const float* proj_b   = (const float*)d_in[13];
    const float* w_w1 = (const float*)d_in[14];
    const float* w_b1 = (const float*)d_in[15];
    const float* w_w2 = (const float*)d_in[16];
    const float* w_b2 = (const float*)d_in[17];
    const float* w_w3 = (const float*)d_in[18];
    const float* w_b3 = (const float*)d_in[19];
    const float* esv  = (const float*)d_in[20];
    float* out = (float*)d_out;

    prep_kernel<<<32, 128>>>(lstm_whh, lstm_bih, lstm_bhh, proj_w,
                             w_w1, w_w2, w_w3);

    mem_mlp_kernel<<<BB, 256>>>(input_set,
                                r_w1, r_b1, r_w2, r_b2, r_w3, r_b3);

    step_kernel<<<BB, 32>>>(lengths, proj_b, w_b1, w_b2, w_b3, esv, out);
}

// round 6
// speedup vs baseline: 2.5672x; 1.6295x over previous
#include <cuda_runtime.h>
#include <cuda_bf16.h>
#include <math.h>

#define BB 4096
#define SS 512
#define EE 64
#define MM 16
#define OUTD 64
#define NSTEPS 5

// Scratch: memories transposed per batch: g_memT[b*MM*SS + m*SS + s]
__device__ float g_memT[(size_t)BB * MM * SS];
// Pre-transposed small weights (k-major) for the recurrence kernel
__device__ float g_whhT[32 * 128];   // [k][j]
__device__ float g_pwT [32 * 16];    // [k][m]
__device__ float g_w1T [32 * 32];    // [k][j]
__device__ float g_w2T [32 * 32];    // [k][j]
__device__ float g_w3T [32 * 64];    // [k][j]
__device__ float g_bsum[128];        // bih + bhh
// Precomputed bf16 B-fragments for the reading MLP (hi/lo split):
//  fid 0..15  : layer1 hi  [c*4+nt]   (c=0..3, nt=0..3)
//  fid 16..31 : layer1 lo
//  fid 32..39 : layer2 hi  [c*4+nt]   (c=0..1, nt=0..3)
//  fid 40..47 : layer2 lo
//  fid 48..51 : layer3 hi  [c*2+nt]   (c=0..1, nt=0..1)
//  fid 52..55 : layer3 lo
__device__ uint2 g_frags[56 * 32];

// ---------------- bf16 pack/split helpers ----------------
__device__ __forceinline__ unsigned int packbf(float lo, float hi) {
    __nv_bfloat162 p = __floats2bfloat162_rn(lo, hi);   // .x -> low 16 bits
    return *reinterpret_cast<unsigned int*>(&p);
}
// v0,v1 -> hi pack + lo(residual) pack
__device__ __forceinline__ void split2(float v0, float v1,
                                       unsigned int& ph, unsigned int& pl) {
    ph = packbf(v0, v1);
    float f0 = __uint_as_float(ph << 16);
    float f1 = __uint_as_float(ph & 0xffff0000u);
    pl = packbf(v0 - f0, v1 - f1);
}

__device__ __forceinline__ void mma16816(float* c, const unsigned int* a, uint2 b) {
    asm("mma.sync.aligned.m16n8k16.row.col.f32.bf16.bf16.f32 "
        "{%0,%1,%2,%3}, {%4,%5,%6,%7}, {%8,%9}, {%0,%1,%2,%3};"
        : "+f"(c[0]), "+f"(c[1]), "+f"(c[2]), "+f"(c[3])
        : "r"(a[0]), "r"(a[1]), "r"(a[2]), "r"(a[3]), "r"(b.x), "r"(b.y));
}

// ---------------------------------------------------------------------------
// Kernel 0: weight transposes + B-fragment construction
// ---------------------------------------------------------------------------
__device__ __forceinline__ uint2 make_bfrag(const float* __restrict__ w,
                                            int K, int n, int kbase, int t, int lo)
{
    float a0 = w[n * K + kbase + 2 * t];
    float a1 = w[n * K + kbase + 2 * t + 1];
    float a8 = w[n * K + kbase + 2 * t + 8];
    float a9 = w[n * K + kbase + 2 * t + 9];
    if (lo) {
        a0 -= __bfloat162float(__float2bfloat16(a0));
        a1 -= __bfloat162float(__float2bfloat16(a1));
        a8 -= __bfloat162float(__float2bfloat16(a8));
        a9 -= __bfloat162float(__float2bfloat16(a9));
    }
    uint2 r;
    r.x = packbf(a0, a1);   // k=2t (low), k=2t+1 (high)
    r.y = packbf(a8, a9);   // k=2t+8, 2t+9
    return r;
}

__global__ void prep_kernel(
    const float* __restrict__ whh, const float* __restrict__ bih,
    const float* __restrict__ bhh, const float* __restrict__ pw,
    const float* __restrict__ w1,  const float* __restrict__ w2,
    const float* __restrict__ w3,
    const float* __restrict__ rw1, const float* __restrict__ rw2,
    const float* __restrict__ rw3)
{
    int gid = blockIdx.x * 128 + threadIdx.x;   // 4096 threads
    int nt  = gridDim.x * 128;
    for (int i = gid; i < 4096; i += nt) { int j = i >> 5, k = i & 31; g_whhT[k*128 + j] = whh[i]; }
    for (int i = gid; i < 512;  i += nt) { int m = i >> 5, k = i & 31; g_pwT [k*16  + m] = pw[i]; }
    for (int i = gid; i < 1024; i += nt) { int j = i >> 5, k = i & 31; g_w1T[k*32 + j] = w1[i];
                                           g_w2T[k*32 + j] = w2[i]; }
    for (int i = gid; i < 2048; i += nt) { int j = i >> 5, k = i & 31; g_w3T[k*64 + j] = w3[i]; }
    if (gid < 128) g_bsum[gid] = bih[gid] + bhh[gid];

    // B-fragments for the reading MLP
    if (gid < 56 * 32) {
        int lane = gid & 31, fid = gid >> 5;
        int g = lane >> 2, t = lane & 3;
        uint2 f;
        if (fid < 32) {
            int lo = (fid >= 16);
            int c  = (fid & 15) >> 2, n4 = fid & 3;
            f = make_bfrag(rw1, 64, n4 * 8 + g, c * 16, t, lo);
        } else if (fid < 48) {
            int lo = (fid >= 40);
            int c  = ((fid - 32) & 7) >> 2, n4 = fid & 3;
            f = make_bfrag(rw2, 32, n4 * 8 + g, c * 16, t, lo);
        } else {
            int lo = (fid >= 52);
            int c  = ((fid - 48) & 3) >> 1, n2 = fid & 1;
            f = make_bfrag(rw3, 32, n2 * 8 + g, c * 16, t, lo);
        }
        g_frags[fid * 32 + lane] = f;
    }
}

// ---------------------------------------------------------------------------
// Kernel 1: reading MLP on tensor cores (bf16 3-term split, fp32 accum).
// Each warp processes 16-row tiles via mma.sync.m16n8k16; layers chain in
// registers (C-frag ownership == A-frag ownership).
// ---------------------------------------------------------------------------
__global__ void __launch_bounds__(256) mem_mlp_kernel(
    const float* __restrict__ x,
    const float* __restrict__ b1,
    const float* __restrict__ b2,
    const float* __restrict__ b3)
{
    __shared__ uint2 sW[56 * 32];
    __shared__ float sb1[32], sb2[32], sb3[16];

    int tid = threadIdx.x;
    #pragma unroll
    for (int i = 0; i < 7; i++) sW[tid + i * 256] = g_frags[tid + i * 256];
    if (tid < 32) { sb1[tid] = b1[tid]; sb2[tid] = b2[tid]; }
    if (tid < 16) sb3[tid] = b3[tid];
    __syncthreads();

    int lane = tid & 31, warp = tid >> 5;
    int g = lane >> 2, t = lane & 3;
    int wg = blockIdx.x * 8 + warp;          // 0..16383

    #pragma unroll 1
    for (int it = 0; it < 8; it++) {
        int tile = it * 16384 + wg;          // 0..131071
        const float* xr0 = x + ((size_t)tile * 16 + g) * 64;
        const float* xr1 = xr0 + 8 * 64;

        // ---- build A fragments for layer 1 (hi/lo) ----
        unsigned int Ah[4][4], Al[4][4];
        #pragma unroll
        for (int c = 0; c < 4; c++) {
            float2 v00 = *(const float2*)(xr0 + c * 16 + 2 * t);
            float2 v01 = *(const float2*)(xr0 + c * 16 + 2 * t + 8);
            float2 v10 = *(const float2*)(xr1 + c * 16 + 2 * t);
            float2 v11 = *(const float2*)(xr1 + c * 16 + 2 * t + 8);
            split2(v00.x, v00.y, Ah[c][0], Al[c][0]);
            split2(v10.x, v10.y, Ah[c][1], Al[c][1]);
            split2(v01.x, v01.y, Ah[c][2], Al[c][2]);
            split2(v11.x, v11.y, Ah[c][3], Al[c][3]);
        }

        // ---- layer 1: K=64, N=32 ----
        float C1[4][4];
        #pragma unroll
        for (int n4 = 0; n4 < 4; n4++) {
            float q0 = sb1[n4 * 8 + 2 * t], q1 = sb1[n4 * 8 + 2 * t + 1];
            C1[n4][0] = q0; C1[n4][1] = q1; C1[n4][2] = q0; C1[n4][3] = q1;
        }
        #pragma unroll
        for (int c = 0; c < 4; c++) {
            #pragma unroll
            for (int n4 = 0; n4 < 4; n4++) {
                uint2 wh = sW[(c * 4 + n4) * 32 + lane];
                uint2 wl = sW[(16 + c * 4 + n4) * 32 + lane];
                mma16816(C1[n4], Ah[c], wh);
                mma16816(C1[n4], Al[c], wh);
                mma16816(C1[n4], Ah[c], wl);
            }
        }

        // ---- relu + split -> A2 ----
        unsigned int A2h[2][4], A2l[2][4];
        #pragma unroll
        for (int cc = 0; cc < 2; cc++) {
            #pragma unroll
            for (int h = 0; h < 2; h++) {
                float p0 = fmaxf(C1[2*cc][2*h],     0.f);
                float p1 = fmaxf(C1[2*cc][2*h + 1], 0.f);
                split2(p0, p1, A2h[cc][h], A2l[cc][h]);
                float q0 = fmaxf(C1[2*cc+1][2*h],     0.f);
                float q1 = fmaxf(C1[2*cc+1][2*h + 1], 0.f);
                split2(q0, q1, A2h[cc][2 + h], A2l[cc][2 + h]);
            }
        }

        // ---- layer 2: K=32, N=32 ----
        float C2[4][4];
        #pragma unroll
        for (int n4 = 0; n4 < 4; n4++) {
            float q0 = sb2[n4 * 8 + 2 * t], q1 = sb2[n4 * 8 + 2 * t + 1];
            C2[n4][0] = q0; C2[n4][1] = q1; C2[n4][2] = q0; C2[n4][3] = q1;
        }
        #pragma unroll
        for (int c = 0; c < 2; c++) {
            #pragma unroll
            for (int n4 = 0; n4 < 4; n4++) {
                uint2 wh = sW[(32 + c * 4 + n4) * 32 + lane];
                uint2 wl = sW[(40 + c * 4 + n4) * 32 + lane];
                mma16816(C2[n4], A2h[c], wh);
                mma16816(C2[n4], A2l[c], wh);
                mma16816(C2[n4], A2h[c], wl);
            }
        }

        // ---- relu + split -> A3 ----
        unsigned int A3h[2][4], A3l[2][4];
        #pragma unroll
        for (int cc = 0; cc < 2; cc++) {
            #pragma unroll
            for (int h = 0; h < 2; h++) {
                float p0 = fmaxf(C2[2*cc][2*h],     0.f);
                float p1 = fmaxf(C2[2*cc][2*h + 1], 0.f);
                split2(p0, p1, A3h[cc][h], A3l[cc][h]);
                float q0 = fmaxf(C2[2*cc+1][2*h],     0.f);
                float q1 = fmaxf(C2[2*cc+1][2*h + 1], 0.f);
                split2(q0, q1, A3h[cc][2 + h], A3l[cc][2 + h]);
            }
        }

        // ---- layer 3: K=32, N=16 (linear) ----
        float C3[2][4];
        #pragma unroll
        for (int n2 = 0; n2 < 2; n2++) {
            float q0 = sb3[n2 * 8 + 2 * t], q1 = sb3[n2 * 8 + 2 * t + 1];
            C3[n2][0] = q0; C3[n2][1] = q1; C3[n2][2] = q0; C3[n2][3] = q1;
        }
        #pragma unroll
        for (int c = 0; c < 2; c++) {
            #pragma unroll
            for (int n2 = 0; n2 < 2; n2++) {
                uint2 wh = sW[(48 + c * 2 + n2) * 32 + lane];
                uint2 wl = sW[(52 + c * 2 + n2) * 32 + lane];
                mma16816(C3[n2], A3h[c], wh);
                mma16816(C3[n2], A3l[c], wh);
                mma16816(C3[n2], A3h[c], wl);
            }
        }

        // ---- store transposed into g_memT[b][m][s] ----
        int R  = tile * 16;
        int b  = R >> 9;
        int s0 = (R & 511) + g;
        int s1 = s0 + 8;
        float* outb = g_memT + (size_t)b * 8192;
        #pragma unroll
        for (int n2 = 0; n2 < 2; n2++) {
            int m0 = n2 * 8 + 2 * t;
            outb[m0 * 512 + s0]       = C3[n2][0];
            outb[(m0 + 1) * 512 + s0] = C3[n2][1];
            outb[m0 * 512 + s1]       = C3[n2][2];
            outb[(m0 + 1) * 512 + s1] = C3[n2][3];
        }
    }
}

// ---------------------------------------------------------------------------
// Kernel 2: ONE WARP PER BATCH, fully vectorized attention (unchanged R5).
// ---------------------------------------------------------------------------
__device__ __forceinline__ float sigmoidf_(float x) {
    return 1.f / (1.f + __expf(-x));
}

__global__ void __launch_bounds__(32) step_kernel(
    const int*   __restrict__ lengths,
    const float* __restrict__ pb_,   // 16
    const float* __restrict__ b1,    // 32
    const float* __restrict__ b2,    // 32
    const float* __restrict__ b3,    // 64
    const float* __restrict__ esv_,  // 64
    float*       __restrict__ out)   // (B,64)
{
    __shared__ __align__(16) float memT[MM * SS];   // 32 KB [m*512 + s]

    const unsigned FULL = 0xffffffffu;
    int b    = blockIdx.x;
    int lane = threadIdx.x;

    float bs0 = g_bsum[lane];
    float bs1 = g_bsum[32 + lane];
    float bs2 = g_bsum[64 + lane];
    float bs3 = g_bsum[96 + lane];
    float pbr = pb_[lane & 15];
    float b1r = b1[lane];
    float b2r = b2[lane];
    float b3r0 = b3[lane],  b3r1 = b3[32 + lane];
    float ev0  = esv_[lane], ev1 = esv_[32 + lane];

    {
        const float4* gm = (const float4*)(g_memT + (size_t)b * (MM * SS));
        float4* dst = (float4*)memT;
        #pragma unroll
        for (int i = lane; i < 2048; i += 32) dst[i] = gm[i];
    }
    int len  = lengths[b];
    int slen = (len > 0) ? len : 1;
    __syncwarp();

    const float4* memT4 = (const float4*)memT;

    float qstar = 0.f;
    float c     = 0.f;

    #pragma unroll 1
    for (int step = 0; step < NSTEPS; step++) {
        float a0 = bs0, a1 = bs1, a2 = bs2, a3 = bs3;
        #pragma unroll
        for (int k = 0; k < 32; k++) {
            float qk = __shfl_sync(FULL, qstar, k);
            const float* wr = g_whhT + k * 128;
            a0 = fmaf(qk, __ldg(wr + lane),       a0);
            a1 = fmaf(qk, __ldg(wr + 32 + lane),  a1);
            a2 = fmaf(qk, __ldg(wr + 64 + lane),  a2);
            a3 = fmaf(qk, __ldg(wr + 96 + lane),  a3);
        }
        float ig = sigmoidf_(a0);
        float fg = sigmoidf_(a1);
        float gg = tanhf(a2);
        float og = sigmoidf_(a3);
        c = fmaf(fg, c, ig * gg);
        float h = og * tanhf(c);

        float aq = pbr;
        {
            int m = lane & 15;
            #pragma unroll
            for (int k = 0; k < 32; k++) {
                float hk = __shfl_sync(FULL, h, k);
                aq = fmaf(hk, __ldg(g_pwT + k * 16 + m), aq);
            }
        }
        float qm[16];
        #pragma unroll
        for (int m = 0; m < 16; m++) qm[m] = __shfl_sync(FULL, aq, m);

        float4 ev[4];
        #pragma unroll
        for (int tt = 0; tt < 4; tt++) {
            float4 acc = make_float4(0.f, 0.f, 0.f, 0.f);
            int base = lane + 32 * tt;
            #pragma unroll
            for (int m = 0; m < 16; m++) {
                float4 v = memT4[m * 128 + base];
                float q = qm[m];
                acc.x = fmaf(q, v.x, acc.x);
                acc.y = fmaf(q, v.y, acc.y);
                acc.z = fmaf(q, v.z, acc.z);
                acc.w = fmaf(q, v.w, acc.w);
            }
            int s = 4 * lane + 128 * tt;
            if (s     >= slen) acc.x = -1e30f;
            if (s + 1 >= slen) acc.y = -1e30f;
            if (s + 2 >= slen) acc.z = -1e30f;
            if (s + 3 >= slen) acc.w = -1e30f;
            ev[tt] = acc;
        }
        float mx = -1e30f;
        #pragma unroll
        for (int tt = 0; tt < 4; tt++)
            mx = fmaxf(mx, fmaxf(fmaxf(ev[tt].x, ev[tt].y), fmaxf(ev[tt].z, ev[tt].w)));
        #pragma unroll
        for (int off = 16; off; off >>= 1)
            mx = fmaxf(mx, __shfl_xor_sync(FULL, mx, off));

        float4 ex[4]; float ssum = 0.f;
        #pragma unroll
        for (int tt = 0; tt < 4; tt++) {
            ex[tt].x = __expf(ev[tt].x - mx);
            ex[tt].y = __expf(ev[tt].y - mx);
            ex[tt].z = __expf(ev[tt].z - mx);
            ex[tt].w = __expf(ev[tt].w - mx);
            ssum += (ex[tt].x + ex[tt].y) + (ex[tt].z + ex[tt].w);
        }
        #pragma unroll
        for (int off = 16; off; off >>= 1)
            ssum += __shfl_xor_sync(FULL, ssum, off);
        float inv = 1.f / ssum;

        float rm[16];
        #pragma unroll
        for (int m = 0; m < 16; m++) rm[m] = 0.f;
        #pragma unroll
        for (int tt = 0; tt < 4; tt++) {
            int base = lane + 32 * tt;
            float4 w = ex[tt];
            #pragma unroll
            for (int m = 0; m < 16; m++) {
                float4 v = memT4[m * 128 + base];
                rm[m] = fmaf(w.x, v.x, fmaf(w.y, v.y, fmaf(w.z, v.z, fmaf(w.w, v.w, rm[m]))));
            }
        }
        #pragma unroll
        for (int m = 0; m < 16; m++) {
            #pragma unroll
            for (int off = 16; off; off >>= 1)
                rm[m] += __shfl_xor_sync(FULL, rm[m], off);
        }

        float nq = 0.f;
        #pragma unroll
        for (int m = 0; m < 16; m++) nq = (lane == m)      ? qm[m]       : nq;
        #pragma unroll
        for (int m = 0; m < 16; m++) nq = (lane == 16 + m) ? rm[m] * inv : nq;
        qstar = nq;
    }

    float x1 = b1r;
    #pragma unroll
    for (int k = 0; k < 32; k++) {
        float qk = __shfl_sync(FULL, qstar, k);
        x1 = fmaf(qk, __ldg(g_w1T + k * 32 + lane), x1);
    }
    x1 = fmaxf(x1, 0.f);

    float x2 = b2r;
    #pragma unroll
    for (int k = 0; k < 32; k++) {
        float hk = __shfl_sync(FULL, x1, k);
        x2 = fmaf(hk, __ldg(g_w2T + k * 32 + lane), x2);
    }
    x2 = fmaxf(x2, 0.f);

    float o0 = b3r0, o1 = b3r1;
    #pragma unroll
    for (int k = 0; k < 32; k++) {
        float hk = __shfl_sync(FULL, x2, k);
        o0 = fmaf(hk, __ldg(g_w3T + k * 64 + lane),      o0);
        o1 = fmaf(hk, __ldg(g_w3T + k * 64 + 32 + lane), o1);
    }
    float* op = out + (size_t)b * OUTD;
    op[lane]      = (len > 0) ? o0 : ev0;
    op[32 + lane] = (len > 0) ? o1 : ev1;
}

// ---------------------------------------------------------------------------
extern "C" void kernel_launch(void* const* d_in, const int* in_sizes, int n_in,
                              void* d_out, int out_size)
{
    const float* input_set = (const float*)d_in[0];
    const int*   lengths   = (const int*)  d_in[1];
    const float* r_w1 = (const float*)d_in[2];
    const float* r_b1 = (const float*)d_in[3];
    const float* r_w2 = (const float*)d_in[4];
    const float* r_b2 = (const float*)d_in[5];
    const float* r_w3 = (const float*)d_in[6];
    const float* r_b3 = (const float*)d_in[7];
    // d_in[8] = lstm_wih (unused: LSTM input is identically zero)
    const float* lstm_whh = (const float*)d_in[9];
    const float* lstm_bih = (const float*)d_in[10];
    const float* lstm_bhh = (const float*)d_in[11];
    const float* proj_w   = (const float*)d_in[12];
    const float* proj_b   = (const float*)d_in[13];
    const float* w_w1 = (const float*)d_in[14];
    const float* w_b1 = (const float*)d_in[15];
    const float* w_w2 = (const float*)d_in[16];
    const float* w_b2 = (const float*)d_in[17];
    const float* w_w3 = (const float*)d_in[18];
    const float* w_b3 = (const float*)d_in[19];
    const float* esv  = (const float*)d_in[20];
    float* out = (float*)d_out;

    prep_kernel<<<32, 128>>>(lstm_whh, lstm_bih, lstm_bhh, proj_w,
                             w_w1, w_w2, w_w3,
                             r_w1, r_w2, r_w3);

    mem_mlp_kernel<<<2048, 256>>>(input_set, r_b1, r_b2, r_b3);

    step_kernel<<<BB, 32>>>(lengths, proj_b, w_b1, w_b2, w_b3, esv, out);
}